// round 15
// baseline (speedup 1.0000x reference)
#include <cuda_runtime.h>
#include <cuda_bf16.h>
#include <cstdint>

// Problem constants
#define B_ 8
#define L_ 2048
#define DM_ 192
#define DI_ 384
#define N_ 16
#define R_ 12
#define M_ (B_ * L_)           // 16384 rows
#define NXZ_ (2 * DI_)          // 768
#define NC_ (R_ + 2 * N_)       // 44
#define NCPAD_ 64
#define NGRP (B_ * DI_)         // 3072
#define LHALF (L_ / 2)          // 1024

// ---------------- scratch (static device allocations; no cudaMalloc) -------
__device__ float g_u[M_ * DI_];
__device__ float g_z[M_ * DI_];
__device__ float g_dts[M_ * R_];
__device__ float2 g_DU[M_ * DI_];     // (delta, u) packed
__device__ float2 g_BC[M_ * N_];      // (B_n, C_n) packed
__device__ float g_y[M_ * DI_];
__device__ float2 g_Hmid[NGRP * 8];   // state at t=LHALF, (h_2l, h_2l+1) per lane
__device__ __nv_bfloat16 g_xhi[M_ * DM_];
__device__ __nv_bfloat16 g_xlo[M_ * DM_];
__device__ __nv_bfloat16 g_whi[NXZ_ * DM_];
__device__ __nv_bfloat16 g_wlo[NXZ_ * DM_];
__device__ __nv_bfloat16 g_xpwhi[NCPAD_ * DI_];
__device__ __nv_bfloat16 g_xpwlo[NCPAD_ * DI_];
__device__ __nv_bfloat16 g_yhi[M_ * DI_];
__device__ __nv_bfloat16 g_ylo[M_ * DI_];
__device__ __nv_bfloat16 g_wohi[DM_ * DI_];
__device__ __nv_bfloat16 g_wolo[DM_ * DI_];

// ============================================================================
// helpers
// ============================================================================
__device__ __forceinline__ uint32_t smem_u32(const void* p) {
    uint32_t a;
    asm("{ .reg .u64 t; cvta.to.shared.u64 t, %1; cvt.u32.u64 %0, t; }"
        : "=r"(a) : "l"(p));
    return a;
}

__device__ __forceinline__ void ldm_x4(uint32_t* r, uint32_t addr) {
    asm volatile("ldmatrix.sync.aligned.m8n8.x4.shared.b16 {%0,%1,%2,%3}, [%4];"
        : "=r"(r[0]), "=r"(r[1]), "=r"(r[2]), "=r"(r[3]) : "r"(addr));
}
__device__ __forceinline__ void ldm_x2(uint32_t* r, uint32_t addr) {
    asm volatile("ldmatrix.sync.aligned.m8n8.x2.shared.b16 {%0,%1}, [%2];"
        : "=r"(r[0]), "=r"(r[1]) : "r"(addr));
}
__device__ __forceinline__ void mma16816(float* c, const uint32_t* a, const uint32_t* b) {
    asm volatile(
        "mma.sync.aligned.m16n8k16.row.col.f32.bf16.bf16.f32 "
        "{%0,%1,%2,%3}, {%4,%5,%6,%7}, {%8,%9}, {%0,%1,%2,%3};"
        : "+f"(c[0]), "+f"(c[1]), "+f"(c[2]), "+f"(c[3])
        : "r"(a[0]), "r"(a[1]), "r"(a[2]), "r"(a[3]), "r"(b[0]), "r"(b[1]));
}

__device__ __forceinline__ __nv_bfloat162 split_hi2(float a, float b,
                                                    __nv_bfloat162& lo2) {
    __nv_bfloat162 h;
    h.x = __float2bfloat16_rn(a);
    h.y = __float2bfloat16_rn(b);
    lo2.x = __float2bfloat16_rn(a - __bfloat162float(h.x));
    lo2.y = __float2bfloat16_rn(b - __bfloat162float(h.y));
    return h;
}

// ============================================================================
// K0: fp32 -> bf16 hi + residual lo
// ============================================================================
__global__ __launch_bounds__(256) void conv_split(
    const float* __restrict__ src, __nv_bfloat16* __restrict__ hi,
    __nv_bfloat16* __restrict__ lo, int n4)
{
    int i = blockIdx.x * blockDim.x + threadIdx.x;
    if (i >= n4) return;
    float4 v = ((const float4*)src)[i];
    __nv_bfloat162 l0, l1;
    __nv_bfloat162 h0 = split_hi2(v.x, v.y, l0);
    __nv_bfloat162 h1 = split_hi2(v.z, v.w, l1);
    ((__nv_bfloat162*)hi)[2 * i] = h0; ((__nv_bfloat162*)hi)[2 * i + 1] = h1;
    ((__nv_bfloat162*)lo)[2 * i] = l0; ((__nv_bfloat162*)lo)[2 * i + 1] = l1;
}

// padded: dst NCPAD_ rows, src NC_ rows of 384, rest zero
__global__ __launch_bounds__(256) void conv_split_pad44(
    const float* __restrict__ src, __nv_bfloat16* __restrict__ hi,
    __nv_bfloat16* __restrict__ lo)
{
    int i = blockIdx.x * blockDim.x + threadIdx.x;
    const int n4 = NCPAD_ * DI_ / 4;
    if (i >= n4) return;
    const int row = i / (DI_ / 4);
    float4 v = make_float4(0.f, 0.f, 0.f, 0.f);
    if (row < NC_) v = ((const float4*)src)[i];
    __nv_bfloat162 l0, l1;
    __nv_bfloat162 h0 = split_hi2(v.x, v.y, l0);
    __nv_bfloat162 h1 = split_hi2(v.z, v.w, l1);
    ((__nv_bfloat162*)hi)[2 * i] = h0; ((__nv_bfloat162*)hi)[2 * i + 1] = h1;
    ((__nv_bfloat162*)lo)[2 * i] = l0; ((__nv_bfloat162*)lo)[2 * i + 1] = l1;
}

// ============================================================================
// Tensor-core GEMM (bf16 split, fp32 accum): acc = Ahi*Whi + Ahi*Wlo + Alo*Whi
//   8 warps (4x2), BK=32.   (R8/R12 known-good: ldm_x2 for B, regs=128)
// ============================================================================
#define LDSB 40

template<int BM, int BN, int KDIM, int EPI, int LDO>
__global__ __launch_bounds__(256) void gemm_mma(
    const __nv_bfloat16* __restrict__ Ahi, const __nv_bfloat16* __restrict__ Alo,
    const __nv_bfloat16* __restrict__ Whi, const __nv_bfloat16* __restrict__ Wlo,
    float* __restrict__ O0, float* __restrict__ O1)
{
    constexpr int WM = BM / 4;
    constexpr int WN = BN / 2;
    constexpr int MI = WM / 16;
    constexpr int NI = WN / 8;

    __shared__ __align__(16) __nv_bfloat16 sAh[BM * LDSB];
    __shared__ __align__(16) __nv_bfloat16 sAl[BM * LDSB];
    __shared__ __align__(16) __nv_bfloat16 sWh[BN * LDSB];
    __shared__ __align__(16) __nv_bfloat16 sWl[BN * LDSB];

    const int tid = threadIdx.x;
    const int wid = tid >> 5, lane = tid & 31;
    const int wr = wid >> 1, wc = wid & 1;
    const int bm = blockIdx.x * BM;
    const int bn = blockIdx.y * BN;

    const uint32_t sAh32 = smem_u32(sAh), sAl32 = smem_u32(sAl);
    const uint32_t sWh32 = smem_u32(sWh), sWl32 = smem_u32(sWl);

    float acc[MI][NI][4];
#pragma unroll
    for (int i = 0; i < MI; i++)
#pragma unroll
        for (int j = 0; j < NI; j++)
#pragma unroll
            for (int e = 0; e < 4; e++) acc[i][j][e] = 0.f;

    for (int k0 = 0; k0 < KDIM; k0 += 32) {
#pragma unroll
        for (int idx = tid; idx < BM * 4; idx += 256) {
            const int row = idx >> 2, c = idx & 3;
            const size_t go = (size_t)(bm + row) * KDIM + k0 + c * 8;
            const int so = row * LDSB + c * 8;
            *(float4*)&sAh[so] = *(const float4*)&Ahi[go];
            *(float4*)&sAl[so] = *(const float4*)&Alo[go];
        }
#pragma unroll
        for (int idx = tid; idx < BN * 4; idx += 256) {
            const int row = idx >> 2, c = idx & 3;
            const size_t go = (size_t)(bn + row) * KDIM + k0 + c * 8;
            const int so = row * LDSB + c * 8;
            *(float4*)&sWh[so] = *(const float4*)&Whi[go];
            *(float4*)&sWl[so] = *(const float4*)&Wlo[go];
        }
        __syncthreads();

#pragma unroll
        for (int ks = 0; ks < 32; ks += 16) {
            uint32_t ah[MI][4], al[MI][4];
#pragma unroll
            for (int mi = 0; mi < MI; mi++) {
                const int row = wr * WM + mi * 16 + (lane & 15);
                const int col = ks + ((lane >> 4) << 3);
                const uint32_t off = (uint32_t)(row * LDSB + col) * 2;
                ldm_x4(ah[mi], sAh32 + off);
                ldm_x4(al[mi], sAl32 + off);
            }
            uint32_t bh[NI][2], bl[NI][2];
#pragma unroll
            for (int ni = 0; ni < NI; ni++) {
                const int row = wc * WN + ni * 8 + (lane & 7);
                const int col = ks + ((lane >> 3) & 1) * 8;
                const uint32_t off = (uint32_t)(row * LDSB + col) * 2;
                ldm_x2(bh[ni], sWh32 + off);
                ldm_x2(bl[ni], sWl32 + off);
            }
#pragma unroll
            for (int mi = 0; mi < MI; mi++)
#pragma unroll
                for (int ni = 0; ni < NI; ni++) {
                    mma16816(acc[mi][ni], ah[mi], bh[ni]);
                    mma16816(acc[mi][ni], ah[mi], bl[ni]);
                    mma16816(acc[mi][ni], al[mi], bh[ni]);
                }
        }
        __syncthreads();
    }

    const int g = lane >> 2, tig = lane & 3;
#pragma unroll
    for (int mi = 0; mi < MI; mi++) {
#pragma unroll
        for (int ni = 0; ni < NI; ni++) {
            const int colg = bn + wc * WN + ni * 8 + tig * 2;
            float v[4] = {acc[mi][ni][0], acc[mi][ni][1],
                          acc[mi][ni][2], acc[mi][ni][3]};
#pragma unroll
            for (int half = 0; half < 2; half++) {
                const int row = bm + wr * WM + mi * 16 + g + half * 8;
                float o0 = v[2 * half], o1 = v[2 * half + 1];
                if (EPI == 0) {
                    *(float2*)&O0[(size_t)row * LDO + colg] = make_float2(o0, o1);
                } else {
                    o0 = o0 / (1.f + __expf(-o0));
                    o1 = o1 / (1.f + __expf(-o1));
                    if (colg < DI_) {
                        *(float2*)&O0[(size_t)row * LDO + colg] = make_float2(o0, o1);
                    } else {
                        *(float2*)&O1[(size_t)row * LDO + colg - DI_] =
                            make_float2(o0, o1);
                    }
                }
            }
        }
    }
}

// ============================================================================
// K2a: dbl = u @ xpw^T  (u fp32 -> bf16 split on the fly during staging).
// ============================================================================
__global__ __launch_bounds__(256) void k2a_gemm(
    const float* __restrict__ U,
    const __nv_bfloat16* __restrict__ Whi, const __nv_bfloat16* __restrict__ Wlo,
    float* __restrict__ DTS, float* __restrict__ BCf)
{
    constexpr int BM = 64, BN = 64;
    constexpr int NI = 4;

    __shared__ __align__(16) __nv_bfloat16 sAh[BM * LDSB];
    __shared__ __align__(16) __nv_bfloat16 sAl[BM * LDSB];
    __shared__ __align__(16) __nv_bfloat16 sWh[BN * LDSB];
    __shared__ __align__(16) __nv_bfloat16 sWl[BN * LDSB];

    const int tid = threadIdx.x;
    const int wid = tid >> 5, lane = tid & 31;
    const int wr = wid >> 1, wc = wid & 1;
    const int bm = blockIdx.x * BM;

    const uint32_t sAh32 = smem_u32(sAh), sAl32 = smem_u32(sAl);
    const uint32_t sWh32 = smem_u32(sWh), sWl32 = smem_u32(sWl);

    float acc[NI][4];
#pragma unroll
    for (int j = 0; j < NI; j++)
#pragma unroll
        for (int e = 0; e < 4; e++) acc[j][e] = 0.f;

    for (int k0 = 0; k0 < DI_; k0 += 32) {
#pragma unroll
        for (int it = 0; it < 2; it++) {
            const int idx = tid + it * 256;
            const int row = idx >> 3, c4 = idx & 7;
            float4 v = *(const float4*)&U[(size_t)(bm + row) * DI_ + k0 + c4 * 4];
            __nv_bfloat162 l0, l1;
            __nv_bfloat162 h0 = split_hi2(v.x, v.y, l0);
            __nv_bfloat162 h1 = split_hi2(v.z, v.w, l1);
            const int so = row * LDSB + c4 * 4;
            *(__nv_bfloat162*)&sAh[so] = h0; *(__nv_bfloat162*)&sAh[so + 2] = h1;
            *(__nv_bfloat162*)&sAl[so] = l0; *(__nv_bfloat162*)&sAl[so + 2] = l1;
        }
#pragma unroll
        for (int idx = tid; idx < BN * 4; idx += 256) {
            const int row = idx >> 2, c = idx & 3;
            const size_t go = (size_t)row * DI_ + k0 + c * 8;
            const int so = row * LDSB + c * 8;
            *(float4*)&sWh[so] = *(const float4*)&Whi[go];
            *(float4*)&sWl[so] = *(const float4*)&Wlo[go];
        }
        __syncthreads();

#pragma unroll
        for (int ks = 0; ks < 32; ks += 16) {
            uint32_t ah[4], al[4];
            {
                const int row = wr * 16 + (lane & 15);
                const int col = ks + ((lane >> 4) << 3);
                const uint32_t off = (uint32_t)(row * LDSB + col) * 2;
                ldm_x4(ah, sAh32 + off);
                ldm_x4(al, sAl32 + off);
            }
            uint32_t bh[NI][2], bl[NI][2];
#pragma unroll
            for (int ni = 0; ni < NI; ni++) {
                const int row = wc * 32 + ni * 8 + (lane & 7);
                const int col = ks + ((lane >> 3) & 1) * 8;
                const uint32_t off = (uint32_t)(row * LDSB + col) * 2;
                ldm_x2(bh[ni], sWh32 + off);
                ldm_x2(bl[ni], sWl32 + off);
            }
#pragma unroll
            for (int ni = 0; ni < NI; ni++) {
                mma16816(acc[ni], ah, bh[ni]);
                mma16816(acc[ni], ah, bl[ni]);
                mma16816(acc[ni], al, bh[ni]);
            }
        }
        __syncthreads();
    }

    const int g = lane >> 2, tig = lane & 3;
#pragma unroll
    for (int ni = 0; ni < NI; ni++) {
        const int colg = wc * 32 + ni * 8 + tig * 2;
#pragma unroll
        for (int half = 0; half < 2; half++) {
            const int row = bm + wr * 16 + g + half * 8;
            const float o0 = acc[ni][2 * half], o1 = acc[ni][2 * half + 1];
            if (colg < R_) {
                *(float2*)&DTS[(size_t)row * R_ + colg] = make_float2(o0, o1);
            } else if (colg < R_ + N_) {
                const int n = colg - R_;
                BCf[(size_t)row * 32 + 2 * n] = o0;
                BCf[(size_t)row * 32 + 2 * n + 2] = o1;
            } else if (colg < NC_) {
                const int n = colg - R_ - N_;
                BCf[(size_t)row * 32 + 2 * n + 1] = o0;
                BCf[(size_t)row * 32 + 2 * n + 3] = o1;
            }
        }
    }
}

// ============================================================================
// K2b: DU = (softplus(dts @ DTW^T + DTB), u)   packed float2
// ============================================================================
__device__ __forceinline__ float softplusf(float x) {
    return (x > 20.f) ? x : log1pf(__expf(x));
}

__global__ __launch_bounds__(256) void k2b_delta(
    const float* __restrict__ DTS, const float* __restrict__ U,
    const float* __restrict__ DTW, const float* __restrict__ DTB,
    float2* __restrict__ DU)
{
    __shared__ float sdtwT[R_][DI_];
    __shared__ float sdts[128 * R_];
    __shared__ float sdtb[DI_];

    const int tid = threadIdx.x;
    const int row0 = blockIdx.x * 128;

    for (int i = tid; i < DI_ * R_; i += 256) {
        int d = i / R_, j = i - d * R_;
        sdtwT[j][d] = DTW[i];
    }
    for (int i = tid; i < 128 * R_; i += 256)
        sdts[i] = DTS[(size_t)row0 * R_ + i];
    for (int i = tid; i < DI_; i += 256) sdtb[i] = DTB[i];
    __syncthreads();

    for (int o = tid; o < 128 * DI_; o += 256) {
        const int r = o / DI_, d = o - r * DI_;
        float acc = sdtb[d];
        const float* ds = &sdts[r * R_];
#pragma unroll
        for (int j = 0; j < R_; j++) acc = fmaf(ds[j], sdtwT[j][d], acc);
        const size_t m = (size_t)(row0 + r) * DI_ + d;
        DU[m] = make_float2(softplusf(acc), U[m]);
    }
}

// ============================================================================
// K3pre: state-only scan of the first half (t < LHALF) per (b,d) group.
//   8 lanes/group, 2 states/lane; NO shuffles, NO Y stores.
//   Output: exact state at t = LHALF.
// ============================================================================
#define K3_UNR 8

__global__ __launch_bounds__(32) void k3_pre(
    const float2* __restrict__ DU, const float4* __restrict__ BC4,
    const float* __restrict__ A_logs, float2* __restrict__ Hmid)
{
    const int tid = threadIdx.x;
    const int gid = (blockIdx.x * 32 + tid) >> 3;
    const int l = tid & 7;
    const int b = gid / DI_;
    const int d = gid - b * DI_;

    const float A1 = -__expf(A_logs[d * N_ + 2 * l]);
    const float A2 = -__expf(A_logs[d * N_ + 2 * l + 1]);

    const float2* duptr = DU + (size_t)b * L_ * DI_ + d;
    const float4* bcptr = BC4 + (size_t)b * L_ * (N_ / 2) + l;

    float2 duA[K3_UNR], duB[K3_UNR];
    float4 bcA[K3_UNR], bcB[K3_UNR];

#pragma unroll
    for (int j = 0; j < K3_UNR; j++) {
        duA[j] = __ldcs(&duptr[(size_t)j * DI_]);
        bcA[j] = __ldcs(&bcptr[(size_t)j * (N_ / 2)]);
    }

    float h1 = 0.f, h2 = 0.f;
    for (int t0 = 0; t0 < LHALF; t0 += 2 * K3_UNR) {
#pragma unroll
        for (int j = 0; j < K3_UNR; j++) {
            duB[j] = __ldcs(&duptr[(size_t)(t0 + K3_UNR + j) * DI_]);
            bcB[j] = __ldcs(&bcptr[(size_t)(t0 + K3_UNR + j) * (N_ / 2)]);
        }
#pragma unroll
        for (int j = 0; j < K3_UNR; j++) {
            const float e1 = __expf(duA[j].x * A1);
            const float e2 = __expf(duA[j].x * A2);
            const float x = duA[j].x * duA[j].y;
            h1 = fmaf(e1, h1, x * bcA[j].x);
            h2 = fmaf(e2, h2, x * bcA[j].z);
        }
        if (t0 + 2 * K3_UNR < LHALF) {
#pragma unroll
            for (int j = 0; j < K3_UNR; j++) {
                duA[j] = __ldcs(&duptr[(size_t)(t0 + 2 * K3_UNR + j) * DI_]);
                bcA[j] = __ldcs(&bcptr[(size_t)(t0 + 2 * K3_UNR + j) * (N_ / 2)]);
            }
        }
#pragma unroll
        for (int j = 0; j < K3_UNR; j++) {
            const float e1 = __expf(duB[j].x * A1);
            const float e2 = __expf(duB[j].x * A2);
            const float x = duB[j].x * duB[j].y;
            h1 = fmaf(e1, h1, x * bcB[j].x);
            h2 = fmaf(e2, h2, x * bcB[j].z);
        }
    }
    Hmid[(size_t)gid * 8 + l] = make_float2(h1, h2);
}

// ============================================================================
// K3: main scan — per (group, half). Half 0 starts at 0, half 1 at Hmid.
//   8 lanes/group, 2 states/lane, float4 BC, 3-level shuffle. (R14 body)
// ============================================================================
__global__ __launch_bounds__(32) void k3_scan(
    const float2* __restrict__ DU, const float4* __restrict__ BC4,
    const float* __restrict__ A_logs, const float* __restrict__ Ds,
    const float2* __restrict__ Hmid, float* __restrict__ Y)
{
    const int tid = threadIdx.x;
    const int gc = (blockIdx.x * 32 + tid) >> 3;     // (group, half)
    const int l = tid & 7;
    const int half = gc & 1;
    const int gid = gc >> 1;
    const int b = gid / DI_;
    const int d = gid - b * DI_;

    const float A1 = -__expf(A_logs[d * N_ + 2 * l]);
    const float A2 = -__expf(A_logs[d * N_ + 2 * l + 1]);
    const float Dd = Ds[d];

    const size_t tbase = (size_t)b * L_ + (size_t)half * LHALF;
    const float2* duptr = DU + tbase * DI_ + d;
    const float4* bcptr = BC4 + tbase * (N_ / 2) + l;
    float* yptr         = Y  + tbase * DI_ + d;

    float h1 = 0.f, h2 = 0.f;
    if (half) {
        const float2 hm = Hmid[(size_t)gid * 8 + l];
        h1 = hm.x; h2 = hm.y;
    }

    float2 duA[K3_UNR], duB[K3_UNR];
    float4 bcA[K3_UNR], bcB[K3_UNR];

#pragma unroll
    for (int j = 0; j < K3_UNR; j++) {
        duA[j] = __ldcs(&duptr[(size_t)j * DI_]);
        bcA[j] = __ldcs(&bcptr[(size_t)j * (N_ / 2)]);
    }

    for (int t0 = 0; t0 < LHALF; t0 += 2 * K3_UNR) {
        // prefetch next 8 into B
#pragma unroll
        for (int j = 0; j < K3_UNR; j++) {
            duB[j] = __ldcs(&duptr[(size_t)(t0 + K3_UNR + j) * DI_]);
            bcB[j] = __ldcs(&bcptr[(size_t)(t0 + K3_UNR + j) * (N_ / 2)]);
        }
        // compute from A
#pragma unroll
        for (int j = 0; j < K3_UNR; j++) {
            const float e1 = __expf(duA[j].x * A1);
            const float e2 = __expf(duA[j].x * A2);
            const float x = duA[j].x * duA[j].y;
            h1 = fmaf(e1, h1, x * bcA[j].x);
            h2 = fmaf(e2, h2, x * bcA[j].z);
            float y = fmaf(h1, bcA[j].y, h2 * bcA[j].w);
            y += __shfl_xor_sync(0xffffffffu, y, 4, 8);
            y += __shfl_xor_sync(0xffffffffu, y, 2, 8);
            y += __shfl_xor_sync(0xffffffffu, y, 1, 8);
            if (l == 0) yptr[(size_t)(t0 + j) * DI_] = fmaf(Dd, duA[j].y, y);
        }
        // prefetch following 8 into A (guarded, uniform branch)
        if (t0 + 2 * K3_UNR < LHALF) {
#pragma unroll
            for (int j = 0; j < K3_UNR; j++) {
                duA[j] = __ldcs(&duptr[(size_t)(t0 + 2 * K3_UNR + j) * DI_]);
                bcA[j] = __ldcs(&bcptr[(size_t)(t0 + 2 * K3_UNR + j) * (N_ / 2)]);
            }
        }
        // compute from B
#pragma unroll
        for (int j = 0; j < K3_UNR; j++) {
            const float e1 = __expf(duB[j].x * A1);
            const float e2 = __expf(duB[j].x * A2);
            const float x = duB[j].x * duB[j].y;
            h1 = fmaf(e1, h1, x * bcB[j].x);
            h2 = fmaf(e2, h2, x * bcB[j].z);
            float y = fmaf(h1, bcB[j].y, h2 * bcB[j].w);
            y += __shfl_xor_sync(0xffffffffu, y, 4, 8);
            y += __shfl_xor_sync(0xffffffffu, y, 2, 8);
            y += __shfl_xor_sync(0xffffffffu, y, 1, 8);
            if (l == 0) yptr[(size_t)(t0 + K3_UNR + j) * DI_] = fmaf(Dd, duB[j].y, y);
        }
    }
}

// ============================================================================
// K4a: yln = (LayerNorm(y)*gamma+beta)*z, emitted as bf16 hi/lo split
// ============================================================================
__global__ __launch_bounds__(256) void k4a_ln(
    const float* __restrict__ Y, const float* __restrict__ Zg,
    const float* __restrict__ gamma, const float* __restrict__ beta,
    __nv_bfloat16* __restrict__ Yhi, __nv_bfloat16* __restrict__ Ylo)
{
    const int tid = threadIdx.x;
    const int warp = tid >> 5, lane = tid & 31;
    const int row = blockIdx.x * 8 + warp;

    const float* yr = Y  + (size_t)row * DI_;
    const float* zr = Zg + (size_t)row * DI_;
    __nv_bfloat16* hr = Yhi + (size_t)row * DI_;
    __nv_bfloat16* lr = Ylo + (size_t)row * DI_;

    float v[12];
    float sum = 0.f, sq = 0.f;
#pragma unroll
    for (int i = 0; i < 12; i++) {
        float t = yr[lane + i * 32];
        v[i] = t; sum += t; sq = fmaf(t, t, sq);
    }
#pragma unroll
    for (int o = 16; o; o >>= 1) {
        sum += __shfl_xor_sync(0xffffffffu, sum, o);
        sq  += __shfl_xor_sync(0xffffffffu, sq, o);
    }
    const float mu = sum * (1.f / DI_);
    const float var = sq * (1.f / DI_) - mu * mu;
    const float rs = rsqrtf(var + 1e-5f);
#pragma unroll
    for (int i = 0; i < 12; i++) {
        int k = lane + i * 32;
        float r = fmaf((v[i] - mu) * rs, gamma[k], beta[k]) * zr[k];
        __nv_bfloat16 h = __float2bfloat16_rn(r);
        hr[k] = h;
        lr[k] = __float2bfloat16_rn(r - __bfloat162float(h));
    }
}

// ============================================================================
extern "C" void kernel_launch(void* const* d_in, const int* in_sizes, int n_in,
                              void* d_out, int out_size)
{
    const float* x         = (const float*)d_in[0];
    const float* W_in      = (const float*)d_in[1];
    const float* x_proj_w  = (const float*)d_in[2];
    const float* dt_proj_w = (const float*)d_in[3];
    const float* dt_proj_b = (const float*)d_in[4];
    const float* A_logs    = (const float*)d_in[5];
    const float* Ds        = (const float*)d_in[6];
    const float* ln_gamma  = (const float*)d_in[7];
    const float* ln_beta   = (const float*)d_in[8];
    const float* W_out     = (const float*)d_in[9];
    float* out = (float*)d_out;

    float *u, *z, *dts, *y;
    float2 *du, *bc, *hmid;
    __nv_bfloat16 *xhi, *xlo, *whi, *wlo, *xpwhi, *xpwlo;
    __nv_bfloat16 *yhi, *ylo, *wohi, *wolo;
    cudaGetSymbolAddress((void**)&u, g_u);
    cudaGetSymbolAddress((void**)&z, g_z);
    cudaGetSymbolAddress((void**)&dts, g_dts);
    cudaGetSymbolAddress((void**)&du, g_DU);
    cudaGetSymbolAddress((void**)&bc, g_BC);
    cudaGetSymbolAddress((void**)&hmid, g_Hmid);
    cudaGetSymbolAddress((void**)&y, g_y);
    cudaGetSymbolAddress((void**)&xhi, g_xhi);
    cudaGetSymbolAddress((void**)&xlo, g_xlo);
    cudaGetSymbolAddress((void**)&whi, g_whi);
    cudaGetSymbolAddress((void**)&wlo, g_wlo);
    cudaGetSymbolAddress((void**)&xpwhi, g_xpwhi);
    cudaGetSymbolAddress((void**)&xpwlo, g_xpwlo);
    cudaGetSymbolAddress((void**)&yhi, g_yhi);
    cudaGetSymbolAddress((void**)&ylo, g_ylo);
    cudaGetSymbolAddress((void**)&wohi, g_wohi);
    cudaGetSymbolAddress((void**)&wolo, g_wolo);

    // input conversions
    conv_split<<<(M_ * DM_ / 4 + 255) / 256, 256>>>(x, xhi, xlo, M_ * DM_ / 4);
    conv_split<<<(NXZ_ * DM_ / 4 + 255) / 256, 256>>>(W_in, whi, wlo, NXZ_ * DM_ / 4);
    conv_split_pad44<<<(NCPAD_ * DI_ / 4 + 255) / 256, 256>>>(x_proj_w, xpwhi, xpwlo);

    // K1: u|z = silu(x @ W_in^T)
    dim3 g1(M_ / 128, NXZ_ / 128);
    gemm_mma<128, 128, DM_, 1, DI_><<<g1, 256>>>(xhi, xlo, whi, wlo, u, z);

    // K2a: dbl = u @ xpw^T -> dts | BC packed
    k2a_gemm<<<M_ / 64, 256>>>(u, xpwhi, xpwlo, dts, (float*)bc);

    // K2b: DU = (softplus(dts @ dtw^T + b), u)
    k2b_delta<<<M_ / 128, 256>>>(dts, u, dt_proj_w, dt_proj_b, du);

    // K3: two-pass scan — state-only pre over first half, then both halves
    k3_pre<<<(NGRP * 8) / 32, 32>>>(du, (const float4*)bc, A_logs, hmid);
    k3_scan<<<(NGRP * 2 * 8) / 32, 32>>>(du, (const float4*)bc, A_logs, Ds,
                                         hmid, y);

    conv_split<<<(DM_ * DI_ / 4 + 255) / 256, 256>>>(W_out, wohi, wolo, DM_ * DI_ / 4);

    k4a_ln<<<M_ / 8, 256>>>(y, z, ln_gamma, ln_beta, yhi, ylo);

    // K4b: out = yln @ W_out^T
    dim3 g4(M_ / 128, DM_ / 64);
    gemm_mma<128, 64, DI_, 0, DM_><<<g4, 256>>>(yhi, ylo, wohi, wolo, out, nullptr);
}

// round 16
// speedup vs baseline: 1.0875x; 1.0875x over previous
#include <cuda_runtime.h>
#include <cuda_bf16.h>
#include <cstdint>

// Problem constants
#define B_ 8
#define L_ 2048
#define DM_ 192
#define DI_ 384
#define N_ 16
#define R_ 12
#define M_ (B_ * L_)           // 16384 rows
#define NXZ_ (2 * DI_)          // 768
#define NC_ (R_ + 2 * N_)       // 44
#define NCPAD_ 64
#define NGRP (B_ * DI_)         // 3072

// ---------------- scratch (static device allocations; no cudaMalloc) -------
__device__ float g_u[M_ * DI_];
__device__ float g_z[M_ * DI_];
__device__ float g_dts[M_ * R_];
__device__ float2 g_DU[M_ * DI_];     // (delta, u) packed
__device__ float2 g_BC[M_ * N_];      // (B_n, C_n) packed
__device__ float g_y[M_ * DI_];
__device__ __nv_bfloat16 g_xhi[M_ * DM_];
__device__ __nv_bfloat16 g_xlo[M_ * DM_];
__device__ __nv_bfloat16 g_whi[NXZ_ * DM_];
__device__ __nv_bfloat16 g_wlo[NXZ_ * DM_];
__device__ __nv_bfloat16 g_xpwhi[NCPAD_ * DI_];
__device__ __nv_bfloat16 g_xpwlo[NCPAD_ * DI_];
__device__ __nv_bfloat16 g_yhi[M_ * DI_];
__device__ __nv_bfloat16 g_ylo[M_ * DI_];
__device__ __nv_bfloat16 g_wohi[DM_ * DI_];
__device__ __nv_bfloat16 g_wolo[DM_ * DI_];

// ============================================================================
// helpers
// ============================================================================
__device__ __forceinline__ uint32_t smem_u32(const void* p) {
    uint32_t a;
    asm("{ .reg .u64 t; cvta.to.shared.u64 t, %1; cvt.u32.u64 %0, t; }"
        : "=r"(a) : "l"(p));
    return a;
}

__device__ __forceinline__ void ldm_x4(uint32_t* r, uint32_t addr) {
    asm volatile("ldmatrix.sync.aligned.m8n8.x4.shared.b16 {%0,%1,%2,%3}, [%4];"
        : "=r"(r[0]), "=r"(r[1]), "=r"(r[2]), "=r"(r[3]) : "r"(addr));
}
__device__ __forceinline__ void ldm_x2(uint32_t* r, uint32_t addr) {
    asm volatile("ldmatrix.sync.aligned.m8n8.x2.shared.b16 {%0,%1}, [%2];"
        : "=r"(r[0]), "=r"(r[1]) : "r"(addr));
}
__device__ __forceinline__ void mma16816(float* c, const uint32_t* a, const uint32_t* b) {
    asm volatile(
        "mma.sync.aligned.m16n8k16.row.col.f32.bf16.bf16.f32 "
        "{%0,%1,%2,%3}, {%4,%5,%6,%7}, {%8,%9}, {%0,%1,%2,%3};"
        : "+f"(c[0]), "+f"(c[1]), "+f"(c[2]), "+f"(c[3])
        : "r"(a[0]), "r"(a[1]), "r"(a[2]), "r"(a[3]), "r"(b[0]), "r"(b[1]));
}

__device__ __forceinline__ __nv_bfloat162 split_hi2(float a, float b,
                                                    __nv_bfloat162& lo2) {
    __nv_bfloat162 h;
    h.x = __float2bfloat16_rn(a);
    h.y = __float2bfloat16_rn(b);
    lo2.x = __float2bfloat16_rn(a - __bfloat162float(h.x));
    lo2.y = __float2bfloat16_rn(b - __bfloat162float(h.y));
    return h;
}

// ============================================================================
// K0: fp32 -> bf16 hi + residual lo
// ============================================================================
__global__ __launch_bounds__(256) void conv_split(
    const float* __restrict__ src, __nv_bfloat16* __restrict__ hi,
    __nv_bfloat16* __restrict__ lo, int n4)
{
    int i = blockIdx.x * blockDim.x + threadIdx.x;
    if (i >= n4) return;
    float4 v = ((const float4*)src)[i];
    __nv_bfloat162 l0, l1;
    __nv_bfloat162 h0 = split_hi2(v.x, v.y, l0);
    __nv_bfloat162 h1 = split_hi2(v.z, v.w, l1);
    ((__nv_bfloat162*)hi)[2 * i] = h0; ((__nv_bfloat162*)hi)[2 * i + 1] = h1;
    ((__nv_bfloat162*)lo)[2 * i] = l0; ((__nv_bfloat162*)lo)[2 * i + 1] = l1;
}

// padded: dst NCPAD_ rows, src NC_ rows of 384, rest zero
__global__ __launch_bounds__(256) void conv_split_pad44(
    const float* __restrict__ src, __nv_bfloat16* __restrict__ hi,
    __nv_bfloat16* __restrict__ lo)
{
    int i = blockIdx.x * blockDim.x + threadIdx.x;
    const int n4 = NCPAD_ * DI_ / 4;
    if (i >= n4) return;
    const int row = i / (DI_ / 4);
    float4 v = make_float4(0.f, 0.f, 0.f, 0.f);
    if (row < NC_) v = ((const float4*)src)[i];
    __nv_bfloat162 l0, l1;
    __nv_bfloat162 h0 = split_hi2(v.x, v.y, l0);
    __nv_bfloat162 h1 = split_hi2(v.z, v.w, l1);
    ((__nv_bfloat162*)hi)[2 * i] = h0; ((__nv_bfloat162*)hi)[2 * i + 1] = h1;
    ((__nv_bfloat162*)lo)[2 * i] = l0; ((__nv_bfloat162*)lo)[2 * i + 1] = l1;
}

// ============================================================================
// Tensor-core GEMM (bf16 split, fp32 accum): acc = Ahi*Whi + Ahi*Wlo + Alo*Whi
//   8 warps (4x2), BK=32.   (R8/R12 known-good: ldm_x2 for B, regs=128)
// ============================================================================
#define LDSB 40

template<int BM, int BN, int KDIM, int EPI, int LDO>
__global__ __launch_bounds__(256) void gemm_mma(
    const __nv_bfloat16* __restrict__ Ahi, const __nv_bfloat16* __restrict__ Alo,
    const __nv_bfloat16* __restrict__ Whi, const __nv_bfloat16* __restrict__ Wlo,
    float* __restrict__ O0, float* __restrict__ O1)
{
    constexpr int WM = BM / 4;
    constexpr int WN = BN / 2;
    constexpr int MI = WM / 16;
    constexpr int NI = WN / 8;

    __shared__ __align__(16) __nv_bfloat16 sAh[BM * LDSB];
    __shared__ __align__(16) __nv_bfloat16 sAl[BM * LDSB];
    __shared__ __align__(16) __nv_bfloat16 sWh[BN * LDSB];
    __shared__ __align__(16) __nv_bfloat16 sWl[BN * LDSB];

    const int tid = threadIdx.x;
    const int wid = tid >> 5, lane = tid & 31;
    const int wr = wid >> 1, wc = wid & 1;
    const int bm = blockIdx.x * BM;
    const int bn = blockIdx.y * BN;

    const uint32_t sAh32 = smem_u32(sAh), sAl32 = smem_u32(sAl);
    const uint32_t sWh32 = smem_u32(sWh), sWl32 = smem_u32(sWl);

    float acc[MI][NI][4];
#pragma unroll
    for (int i = 0; i < MI; i++)
#pragma unroll
        for (int j = 0; j < NI; j++)
#pragma unroll
            for (int e = 0; e < 4; e++) acc[i][j][e] = 0.f;

    for (int k0 = 0; k0 < KDIM; k0 += 32) {
#pragma unroll
        for (int idx = tid; idx < BM * 4; idx += 256) {
            const int row = idx >> 2, c = idx & 3;
            const size_t go = (size_t)(bm + row) * KDIM + k0 + c * 8;
            const int so = row * LDSB + c * 8;
            *(float4*)&sAh[so] = *(const float4*)&Ahi[go];
            *(float4*)&sAl[so] = *(const float4*)&Alo[go];
        }
#pragma unroll
        for (int idx = tid; idx < BN * 4; idx += 256) {
            const int row = idx >> 2, c = idx & 3;
            const size_t go = (size_t)(bn + row) * KDIM + k0 + c * 8;
            const int so = row * LDSB + c * 8;
            *(float4*)&sWh[so] = *(const float4*)&Whi[go];
            *(float4*)&sWl[so] = *(const float4*)&Wlo[go];
        }
        __syncthreads();

#pragma unroll
        for (int ks = 0; ks < 32; ks += 16) {
            uint32_t ah[MI][4], al[MI][4];
#pragma unroll
            for (int mi = 0; mi < MI; mi++) {
                const int row = wr * WM + mi * 16 + (lane & 15);
                const int col = ks + ((lane >> 4) << 3);
                const uint32_t off = (uint32_t)(row * LDSB + col) * 2;
                ldm_x4(ah[mi], sAh32 + off);
                ldm_x4(al[mi], sAl32 + off);
            }
            uint32_t bh[NI][2], bl[NI][2];
#pragma unroll
            for (int ni = 0; ni < NI; ni++) {
                const int row = wc * WN + ni * 8 + (lane & 7);
                const int col = ks + ((lane >> 3) & 1) * 8;
                const uint32_t off = (uint32_t)(row * LDSB + col) * 2;
                ldm_x2(bh[ni], sWh32 + off);
                ldm_x2(bl[ni], sWl32 + off);
            }
#pragma unroll
            for (int mi = 0; mi < MI; mi++)
#pragma unroll
                for (int ni = 0; ni < NI; ni++) {
                    mma16816(acc[mi][ni], ah[mi], bh[ni]);
                    mma16816(acc[mi][ni], ah[mi], bl[ni]);
                    mma16816(acc[mi][ni], al[mi], bh[ni]);
                }
        }
        __syncthreads();
    }

    const int g = lane >> 2, tig = lane & 3;
#pragma unroll
    for (int mi = 0; mi < MI; mi++) {
#pragma unroll
        for (int ni = 0; ni < NI; ni++) {
            const int colg = bn + wc * WN + ni * 8 + tig * 2;
            float v[4] = {acc[mi][ni][0], acc[mi][ni][1],
                          acc[mi][ni][2], acc[mi][ni][3]};
#pragma unroll
            for (int half = 0; half < 2; half++) {
                const int row = bm + wr * WM + mi * 16 + g + half * 8;
                float o0 = v[2 * half], o1 = v[2 * half + 1];
                if (EPI == 0) {
                    *(float2*)&O0[(size_t)row * LDO + colg] = make_float2(o0, o1);
                } else {
                    o0 = o0 / (1.f + __expf(-o0));
                    o1 = o1 / (1.f + __expf(-o1));
                    if (colg < DI_) {
                        *(float2*)&O0[(size_t)row * LDO + colg] = make_float2(o0, o1);
                    } else {
                        *(float2*)&O1[(size_t)row * LDO + colg - DI_] =
                            make_float2(o0, o1);
                    }
                }
            }
        }
    }
}

// ============================================================================
// K2a: dbl = u @ xpw^T  (u fp32 -> bf16 split on the fly during staging).
// ============================================================================
__global__ __launch_bounds__(256) void k2a_gemm(
    const float* __restrict__ U,
    const __nv_bfloat16* __restrict__ Whi, const __nv_bfloat16* __restrict__ Wlo,
    float* __restrict__ DTS, float* __restrict__ BCf)
{
    constexpr int BM = 64, BN = 64;
    constexpr int NI = 4;

    __shared__ __align__(16) __nv_bfloat16 sAh[BM * LDSB];
    __shared__ __align__(16) __nv_bfloat16 sAl[BM * LDSB];
    __shared__ __align__(16) __nv_bfloat16 sWh[BN * LDSB];
    __shared__ __align__(16) __nv_bfloat16 sWl[BN * LDSB];

    const int tid = threadIdx.x;
    const int wid = tid >> 5, lane = tid & 31;
    const int wr = wid >> 1, wc = wid & 1;
    const int bm = blockIdx.x * BM;

    const uint32_t sAh32 = smem_u32(sAh), sAl32 = smem_u32(sAl);
    const uint32_t sWh32 = smem_u32(sWh), sWl32 = smem_u32(sWl);

    float acc[NI][4];
#pragma unroll
    for (int j = 0; j < NI; j++)
#pragma unroll
        for (int e = 0; e < 4; e++) acc[j][e] = 0.f;

    for (int k0 = 0; k0 < DI_; k0 += 32) {
#pragma unroll
        for (int it = 0; it < 2; it++) {
            const int idx = tid + it * 256;
            const int row = idx >> 3, c4 = idx & 7;
            float4 v = *(const float4*)&U[(size_t)(bm + row) * DI_ + k0 + c4 * 4];
            __nv_bfloat162 l0, l1;
            __nv_bfloat162 h0 = split_hi2(v.x, v.y, l0);
            __nv_bfloat162 h1 = split_hi2(v.z, v.w, l1);
            const int so = row * LDSB + c4 * 4;
            *(__nv_bfloat162*)&sAh[so] = h0; *(__nv_bfloat162*)&sAh[so + 2] = h1;
            *(__nv_bfloat162*)&sAl[so] = l0; *(__nv_bfloat162*)&sAl[so + 2] = l1;
        }
#pragma unroll
        for (int idx = tid; idx < BN * 4; idx += 256) {
            const int row = idx >> 2, c = idx & 3;
            const size_t go = (size_t)row * DI_ + k0 + c * 8;
            const int so = row * LDSB + c * 8;
            *(float4*)&sWh[so] = *(const float4*)&Whi[go];
            *(float4*)&sWl[so] = *(const float4*)&Wlo[go];
        }
        __syncthreads();

#pragma unroll
        for (int ks = 0; ks < 32; ks += 16) {
            uint32_t ah[4], al[4];
            {
                const int row = wr * 16 + (lane & 15);
                const int col = ks + ((lane >> 4) << 3);
                const uint32_t off = (uint32_t)(row * LDSB + col) * 2;
                ldm_x4(ah, sAh32 + off);
                ldm_x4(al, sAl32 + off);
            }
            uint32_t bh[NI][2], bl[NI][2];
#pragma unroll
            for (int ni = 0; ni < NI; ni++) {
                const int row = wc * 32 + ni * 8 + (lane & 7);
                const int col = ks + ((lane >> 3) & 1) * 8;
                const uint32_t off = (uint32_t)(row * LDSB + col) * 2;
                ldm_x2(bh[ni], sWh32 + off);
                ldm_x2(bl[ni], sWl32 + off);
            }
#pragma unroll
            for (int ni = 0; ni < NI; ni++) {
                mma16816(acc[ni], ah, bh[ni]);
                mma16816(acc[ni], ah, bl[ni]);
                mma16816(acc[ni], al, bh[ni]);
            }
        }
        __syncthreads();
    }

    const int g = lane >> 2, tig = lane & 3;
#pragma unroll
    for (int ni = 0; ni < NI; ni++) {
        const int colg = wc * 32 + ni * 8 + tig * 2;
#pragma unroll
        for (int half = 0; half < 2; half++) {
            const int row = bm + wr * 16 + g + half * 8;
            const float o0 = acc[ni][2 * half], o1 = acc[ni][2 * half + 1];
            if (colg < R_) {
                *(float2*)&DTS[(size_t)row * R_ + colg] = make_float2(o0, o1);
            } else if (colg < R_ + N_) {
                const int n = colg - R_;
                BCf[(size_t)row * 32 + 2 * n] = o0;
                BCf[(size_t)row * 32 + 2 * n + 2] = o1;
            } else if (colg < NC_) {
                const int n = colg - R_ - N_;
                BCf[(size_t)row * 32 + 2 * n + 1] = o0;
                BCf[(size_t)row * 32 + 2 * n + 3] = o1;
            }
        }
    }
}

// ============================================================================
// K2b: DU = (softplus(dts @ DTW^T + DTB), u)   packed float2
// ============================================================================
__device__ __forceinline__ float softplusf(float x) {
    return (x > 20.f) ? x : log1pf(__expf(x));
}

__global__ __launch_bounds__(256) void k2b_delta(
    const float* __restrict__ DTS, const float* __restrict__ U,
    const float* __restrict__ DTW, const float* __restrict__ DTB,
    float2* __restrict__ DU)
{
    __shared__ float sdtwT[R_][DI_];
    __shared__ float sdts[128 * R_];
    __shared__ float sdtb[DI_];

    const int tid = threadIdx.x;
    const int row0 = blockIdx.x * 128;

    for (int i = tid; i < DI_ * R_; i += 256) {
        int d = i / R_, j = i - d * R_;
        sdtwT[j][d] = DTW[i];
    }
    for (int i = tid; i < 128 * R_; i += 256)
        sdts[i] = DTS[(size_t)row0 * R_ + i];
    for (int i = tid; i < DI_; i += 256) sdtb[i] = DTB[i];
    __syncthreads();

    for (int o = tid; o < 128 * DI_; o += 256) {
        const int r = o / DI_, d = o - r * DI_;
        float acc = sdtb[d];
        const float* ds = &sdts[r * R_];
#pragma unroll
        for (int j = 0; j < R_; j++) acc = fmaf(ds[j], sdtwT[j][d], acc);
        const size_t m = (size_t)(row0 + r) * DI_ + d;
        DU[m] = make_float2(softplusf(acc), U[m]);
    }
}

// ============================================================================
// K3: selective scan — 8 lanes per (b,d) group, 2 states per lane,
//   batched butterfly reduction: 7 SHFL + 1 STG per 8 timesteps.
//   Lane l ends holding the full sum for timestep t0+l; across the 4 groups
//   in a warp the stores coalesce into 16B rows.
// ============================================================================
#define K3_UNR 8

__device__ __forceinline__ void k3_reduce_store8(
    float* yv, int l, float* yptr, int t0)
{
    // butterfly: 8 values across 8 lanes -> lane l holds sum for t0+l
#pragma unroll
    for (int i = 0; i < 4; i++) {
        float give = (l & 4) ? yv[i] : yv[i + 4];
        float got = __shfl_xor_sync(0xffffffffu, give, 4, 8);
        yv[i] = ((l & 4) ? yv[i + 4] : yv[i]) + got;
    }
#pragma unroll
    for (int i = 0; i < 2; i++) {
        float give = (l & 2) ? yv[i] : yv[i + 2];
        float got = __shfl_xor_sync(0xffffffffu, give, 2, 8);
        yv[i] = ((l & 2) ? yv[i + 2] : yv[i]) + got;
    }
    {
        float give = (l & 1) ? yv[0] : yv[1];
        float got = __shfl_xor_sync(0xffffffffu, give, 1, 8);
        float tot = ((l & 1) ? yv[1] : yv[0]) + got;
        yptr[(size_t)(t0 + l) * DI_] = tot;
    }
}

__global__ __launch_bounds__(32) void k3_scan(
    const float2* __restrict__ DU, const float4* __restrict__ BC4,
    const float* __restrict__ A_logs, const float* __restrict__ Ds,
    float* __restrict__ Y)
{
    const int tid = threadIdx.x;
    const int gid = (blockIdx.x * 32 + tid) >> 3;   // (b,d) group
    const int l = tid & 7;                           // lane-in-group
    const int b = gid / DI_;
    const int d = gid - b * DI_;

    const float A1 = -__expf(A_logs[d * N_ + 2 * l]);
    const float A2 = -__expf(A_logs[d * N_ + 2 * l + 1]);
    const float Dd = Ds[d];

    const float2* duptr = DU + (size_t)b * L_ * DI_ + d;
    const float4* bcptr = BC4 + (size_t)b * L_ * (N_ / 2) + l;
    float* yptr         = Y  + (size_t)b * L_ * DI_ + d;

    float2 duA[K3_UNR], duB[K3_UNR];
    float4 bcA[K3_UNR], bcB[K3_UNR];

#pragma unroll
    for (int j = 0; j < K3_UNR; j++) {
        duA[j] = __ldcs(&duptr[(size_t)j * DI_]);
        bcA[j] = __ldcs(&bcptr[(size_t)j * (N_ / 2)]);
    }

    float h1 = 0.f, h2 = 0.f;
    for (int t0 = 0; t0 < L_; t0 += 2 * K3_UNR) {
        // prefetch next 8 into B
#pragma unroll
        for (int j = 0; j < K3_UNR; j++) {
            duB[j] = __ldcs(&duptr[(size_t)(t0 + K3_UNR + j) * DI_]);
            bcB[j] = __ldcs(&bcptr[(size_t)(t0 + K3_UNR + j) * (N_ / 2)]);
        }
        // compute from A
        {
            float yv[K3_UNR];
#pragma unroll
            for (int j = 0; j < K3_UNR; j++) {
                const float e1 = __expf(duA[j].x * A1);
                const float e2 = __expf(duA[j].x * A2);
                const float x = duA[j].x * duA[j].y;
                h1 = fmaf(e1, h1, x * bcA[j].x);
                h2 = fmaf(e2, h2, x * bcA[j].z);
                yv[j] = fmaf(h1, bcA[j].y, h2 * bcA[j].w);
                yv[j] += (l == j) ? Dd * duA[j].y : 0.f;
            }
            k3_reduce_store8(yv, l, yptr, t0);
        }
        // prefetch following 8 into A (guarded, uniform branch)
        if (t0 + 2 * K3_UNR < L_) {
#pragma unroll
            for (int j = 0; j < K3_UNR; j++) {
                duA[j] = __ldcs(&duptr[(size_t)(t0 + 2 * K3_UNR + j) * DI_]);
                bcA[j] = __ldcs(&bcptr[(size_t)(t0 + 2 * K3_UNR + j) * (N_ / 2)]);
            }
        }
        // compute from B
        {
            float yv[K3_UNR];
#pragma unroll
            for (int j = 0; j < K3_UNR; j++) {
                const float e1 = __expf(duB[j].x * A1);
                const float e2 = __expf(duB[j].x * A2);
                const float x = duB[j].x * duB[j].y;
                h1 = fmaf(e1, h1, x * bcB[j].x);
                h2 = fmaf(e2, h2, x * bcB[j].z);
                yv[j] = fmaf(h1, bcB[j].y, h2 * bcB[j].w);
                yv[j] += (l == j) ? Dd * duB[j].y : 0.f;
            }
            k3_reduce_store8(yv, l, yptr, t0 + K3_UNR);
        }
    }
}

// ============================================================================
// K4a: yln = (LayerNorm(y)*gamma+beta)*z, emitted as bf16 hi/lo split
// ============================================================================
__global__ __launch_bounds__(256) void k4a_ln(
    const float* __restrict__ Y, const float* __restrict__ Zg,
    const float* __restrict__ gamma, const float* __restrict__ beta,
    __nv_bfloat16* __restrict__ Yhi, __nv_bfloat16* __restrict__ Ylo)
{
    const int tid = threadIdx.x;
    const int warp = tid >> 5, lane = tid & 31;
    const int row = blockIdx.x * 8 + warp;

    const float* yr = Y  + (size_t)row * DI_;
    const float* zr = Zg + (size_t)row * DI_;
    __nv_bfloat16* hr = Yhi + (size_t)row * DI_;
    __nv_bfloat16* lr = Ylo + (size_t)row * DI_;

    float v[12];
    float sum = 0.f, sq = 0.f;
#pragma unroll
    for (int i = 0; i < 12; i++) {
        float t = yr[lane + i * 32];
        v[i] = t; sum += t; sq = fmaf(t, t, sq);
    }
#pragma unroll
    for (int o = 16; o; o >>= 1) {
        sum += __shfl_xor_sync(0xffffffffu, sum, o);
        sq  += __shfl_xor_sync(0xffffffffu, sq, o);
    }
    const float mu = sum * (1.f / DI_);
    const float var = sq * (1.f / DI_) - mu * mu;
    const float rs = rsqrtf(var + 1e-5f);
#pragma unroll
    for (int i = 0; i < 12; i++) {
        int k = lane + i * 32;
        float r = fmaf((v[i] - mu) * rs, gamma[k], beta[k]) * zr[k];
        __nv_bfloat16 h = __float2bfloat16_rn(r);
        hr[k] = h;
        lr[k] = __float2bfloat16_rn(r - __bfloat162float(h));
    }
}

// ============================================================================
extern "C" void kernel_launch(void* const* d_in, const int* in_sizes, int n_in,
                              void* d_out, int out_size)
{
    const float* x         = (const float*)d_in[0];
    const float* W_in      = (const float*)d_in[1];
    const float* x_proj_w  = (const float*)d_in[2];
    const float* dt_proj_w = (const float*)d_in[3];
    const float* dt_proj_b = (const float*)d_in[4];
    const float* A_logs    = (const float*)d_in[5];
    const float* Ds        = (const float*)d_in[6];
    const float* ln_gamma  = (const float*)d_in[7];
    const float* ln_beta   = (const float*)d_in[8];
    const float* W_out     = (const float*)d_in[9];
    float* out = (float*)d_out;

    float *u, *z, *dts, *y;
    float2 *du, *bc;
    __nv_bfloat16 *xhi, *xlo, *whi, *wlo, *xpwhi, *xpwlo;
    __nv_bfloat16 *yhi, *ylo, *wohi, *wolo;
    cudaGetSymbolAddress((void**)&u, g_u);
    cudaGetSymbolAddress((void**)&z, g_z);
    cudaGetSymbolAddress((void**)&dts, g_dts);
    cudaGetSymbolAddress((void**)&du, g_DU);
    cudaGetSymbolAddress((void**)&bc, g_BC);
    cudaGetSymbolAddress((void**)&y, g_y);
    cudaGetSymbolAddress((void**)&xhi, g_xhi);
    cudaGetSymbolAddress((void**)&xlo, g_xlo);
    cudaGetSymbolAddress((void**)&whi, g_whi);
    cudaGetSymbolAddress((void**)&wlo, g_wlo);
    cudaGetSymbolAddress((void**)&xpwhi, g_xpwhi);
    cudaGetSymbolAddress((void**)&xpwlo, g_xpwlo);
    cudaGetSymbolAddress((void**)&yhi, g_yhi);
    cudaGetSymbolAddress((void**)&ylo, g_ylo);
    cudaGetSymbolAddress((void**)&wohi, g_wohi);
    cudaGetSymbolAddress((void**)&wolo, g_wolo);

    // input conversions
    conv_split<<<(M_ * DM_ / 4 + 255) / 256, 256>>>(x, xhi, xlo, M_ * DM_ / 4);
    conv_split<<<(NXZ_ * DM_ / 4 + 255) / 256, 256>>>(W_in, whi, wlo, NXZ_ * DM_ / 4);
    conv_split_pad44<<<(NCPAD_ * DI_ / 4 + 255) / 256, 256>>>(x_proj_w, xpwhi, xpwlo);

    // K1: u|z = silu(x @ W_in^T)
    dim3 g1(M_ / 128, NXZ_ / 128);
    gemm_mma<128, 128, DM_, 1, DI_><<<g1, 256>>>(xhi, xlo, whi, wlo, u, z);

    // K2a: dbl = u @ xpw^T -> dts | BC packed
    k2a_gemm<<<M_ / 64, 256>>>(u, xpwhi, xpwlo, dts, (float*)bc);

    // K2b: DU = (softplus(dts @ dtw^T + b), u)
    k2b_delta<<<M_ / 128, 256>>>(dts, u, dt_proj_w, dt_proj_b, du);

    // K3: scan — butterfly-reduced, batched stores
    k3_scan<<<(NGRP * 8) / 32, 32>>>(du, (const float4*)bc, A_logs, Ds, y);

    conv_split<<<(DM_ * DI_ / 4 + 255) / 256, 256>>>(W_out, wohi, wolo, DM_ * DI_ / 4);

    k4a_ln<<<M_ / 8, 256>>>(y, z, ln_gamma, ln_beta, yhi, ylo);

    // K4b: out = yln @ W_out^T
    dim3 g4(M_ / 128, DM_ / 64);
    gemm_mma<128, 64, DI_, 0, DM_><<<g4, 256>>>(yhi, ylo, wohi, wolo, out, nullptr);
}

// round 17
// speedup vs baseline: 1.1358x; 1.0445x over previous
#include <cuda_runtime.h>
#include <cuda_bf16.h>
#include <cstdint>

// Problem constants
#define B_ 8
#define L_ 2048
#define DM_ 192
#define DI_ 384
#define N_ 16
#define R_ 12
#define M_ (B_ * L_)           // 16384 rows
#define NXZ_ (2 * DI_)          // 768
#define NC_ (R_ + 2 * N_)       // 44
#define NCPAD_ 64
#define NGRP (B_ * DI_)         // 3072

// ---------------- scratch (static device allocations; no cudaMalloc) -------
__device__ float g_u[M_ * DI_];
__device__ float g_z[M_ * DI_];
__device__ float g_dts[M_ * R_];
__device__ float2 g_DU[M_ * DI_];     // (delta, u) packed
__device__ float2 g_BC[M_ * N_];      // (B_n, C_n) packed
__device__ float g_y[M_ * DI_];
__device__ __nv_bfloat16 g_xhi[M_ * DM_];
__device__ __nv_bfloat16 g_xlo[M_ * DM_];
__device__ __nv_bfloat16 g_whi[NXZ_ * DM_];
__device__ __nv_bfloat16 g_wlo[NXZ_ * DM_];
__device__ __nv_bfloat16 g_xpwhi[NCPAD_ * DI_];
__device__ __nv_bfloat16 g_xpwlo[NCPAD_ * DI_];
__device__ __nv_bfloat16 g_yhi[M_ * DI_];
__device__ __nv_bfloat16 g_ylo[M_ * DI_];
__device__ __nv_bfloat16 g_wohi[DM_ * DI_];
__device__ __nv_bfloat16 g_wolo[DM_ * DI_];

// ============================================================================
// helpers
// ============================================================================
__device__ __forceinline__ uint32_t smem_u32(const void* p) {
    uint32_t a;
    asm("{ .reg .u64 t; cvta.to.shared.u64 t, %1; cvt.u32.u64 %0, t; }"
        : "=r"(a) : "l"(p));
    return a;
}

__device__ __forceinline__ void ldm_x4(uint32_t* r, uint32_t addr) {
    asm volatile("ldmatrix.sync.aligned.m8n8.x4.shared.b16 {%0,%1,%2,%3}, [%4];"
        : "=r"(r[0]), "=r"(r[1]), "=r"(r[2]), "=r"(r[3]) : "r"(addr));
}
__device__ __forceinline__ void ldm_x2(uint32_t* r, uint32_t addr) {
    asm volatile("ldmatrix.sync.aligned.m8n8.x2.shared.b16 {%0,%1}, [%2];"
        : "=r"(r[0]), "=r"(r[1]) : "r"(addr));
}
__device__ __forceinline__ void mma16816(float* c, const uint32_t* a, const uint32_t* b) {
    asm volatile(
        "mma.sync.aligned.m16n8k16.row.col.f32.bf16.bf16.f32 "
        "{%0,%1,%2,%3}, {%4,%5,%6,%7}, {%8,%9}, {%0,%1,%2,%3};"
        : "+f"(c[0]), "+f"(c[1]), "+f"(c[2]), "+f"(c[3])
        : "r"(a[0]), "r"(a[1]), "r"(a[2]), "r"(a[3]), "r"(b[0]), "r"(b[1]));
}

__device__ __forceinline__ __nv_bfloat162 split_hi2(float a, float b,
                                                    __nv_bfloat162& lo2) {
    __nv_bfloat162 h;
    h.x = __float2bfloat16_rn(a);
    h.y = __float2bfloat16_rn(b);
    lo2.x = __float2bfloat16_rn(a - __bfloat162float(h.x));
    lo2.y = __float2bfloat16_rn(b - __bfloat162float(h.y));
    return h;
}

// ============================================================================
// K0: fp32 -> bf16 hi + residual lo
// ============================================================================
__global__ __launch_bounds__(256) void conv_split(
    const float* __restrict__ src, __nv_bfloat16* __restrict__ hi,
    __nv_bfloat16* __restrict__ lo, int n4)
{
    int i = blockIdx.x * blockDim.x + threadIdx.x;
    if (i >= n4) return;
    float4 v = ((const float4*)src)[i];
    __nv_bfloat162 l0, l1;
    __nv_bfloat162 h0 = split_hi2(v.x, v.y, l0);
    __nv_bfloat162 h1 = split_hi2(v.z, v.w, l1);
    ((__nv_bfloat162*)hi)[2 * i] = h0; ((__nv_bfloat162*)hi)[2 * i + 1] = h1;
    ((__nv_bfloat162*)lo)[2 * i] = l0; ((__nv_bfloat162*)lo)[2 * i + 1] = l1;
}

// padded: dst NCPAD_ rows, src NC_ rows of 384, rest zero
__global__ __launch_bounds__(256) void conv_split_pad44(
    const float* __restrict__ src, __nv_bfloat16* __restrict__ hi,
    __nv_bfloat16* __restrict__ lo)
{
    int i = blockIdx.x * blockDim.x + threadIdx.x;
    const int n4 = NCPAD_ * DI_ / 4;
    if (i >= n4) return;
    const int row = i / (DI_ / 4);
    float4 v = make_float4(0.f, 0.f, 0.f, 0.f);
    if (row < NC_) v = ((const float4*)src)[i];
    __nv_bfloat162 l0, l1;
    __nv_bfloat162 h0 = split_hi2(v.x, v.y, l0);
    __nv_bfloat162 h1 = split_hi2(v.z, v.w, l1);
    ((__nv_bfloat162*)hi)[2 * i] = h0; ((__nv_bfloat162*)hi)[2 * i + 1] = h1;
    ((__nv_bfloat162*)lo)[2 * i] = l0; ((__nv_bfloat162*)lo)[2 * i + 1] = l1;
}

// ============================================================================
// Tensor-core GEMM (bf16 split, fp32 accum): acc = Ahi*Whi + Ahi*Wlo + Alo*Whi
//   8 warps (4x2), BK=32.   (R8/R12 known-good: ldm_x2 for B, regs=128)
// ============================================================================
#define LDSB 40

template<int BM, int BN, int KDIM, int EPI, int LDO>
__global__ __launch_bounds__(256) void gemm_mma(
    const __nv_bfloat16* __restrict__ Ahi, const __nv_bfloat16* __restrict__ Alo,
    const __nv_bfloat16* __restrict__ Whi, const __nv_bfloat16* __restrict__ Wlo,
    float* __restrict__ O0, float* __restrict__ O1)
{
    constexpr int WM = BM / 4;
    constexpr int WN = BN / 2;
    constexpr int MI = WM / 16;
    constexpr int NI = WN / 8;

    __shared__ __align__(16) __nv_bfloat16 sAh[BM * LDSB];
    __shared__ __align__(16) __nv_bfloat16 sAl[BM * LDSB];
    __shared__ __align__(16) __nv_bfloat16 sWh[BN * LDSB];
    __shared__ __align__(16) __nv_bfloat16 sWl[BN * LDSB];

    const int tid = threadIdx.x;
    const int wid = tid >> 5, lane = tid & 31;
    const int wr = wid >> 1, wc = wid & 1;
    const int bm = blockIdx.x * BM;
    const int bn = blockIdx.y * BN;

    const uint32_t sAh32 = smem_u32(sAh), sAl32 = smem_u32(sAl);
    const uint32_t sWh32 = smem_u32(sWh), sWl32 = smem_u32(sWl);

    float acc[MI][NI][4];
#pragma unroll
    for (int i = 0; i < MI; i++)
#pragma unroll
        for (int j = 0; j < NI; j++)
#pragma unroll
            for (int e = 0; e < 4; e++) acc[i][j][e] = 0.f;

    for (int k0 = 0; k0 < KDIM; k0 += 32) {
#pragma unroll
        for (int idx = tid; idx < BM * 4; idx += 256) {
            const int row = idx >> 2, c = idx & 3;
            const size_t go = (size_t)(bm + row) * KDIM + k0 + c * 8;
            const int so = row * LDSB + c * 8;
            *(float4*)&sAh[so] = *(const float4*)&Ahi[go];
            *(float4*)&sAl[so] = *(const float4*)&Alo[go];
        }
#pragma unroll
        for (int idx = tid; idx < BN * 4; idx += 256) {
            const int row = idx >> 2, c = idx & 3;
            const size_t go = (size_t)(bn + row) * KDIM + k0 + c * 8;
            const int so = row * LDSB + c * 8;
            *(float4*)&sWh[so] = *(const float4*)&Whi[go];
            *(float4*)&sWl[so] = *(const float4*)&Wlo[go];
        }
        __syncthreads();

#pragma unroll
        for (int ks = 0; ks < 32; ks += 16) {
            uint32_t ah[MI][4], al[MI][4];
#pragma unroll
            for (int mi = 0; mi < MI; mi++) {
                const int row = wr * WM + mi * 16 + (lane & 15);
                const int col = ks + ((lane >> 4) << 3);
                const uint32_t off = (uint32_t)(row * LDSB + col) * 2;
                ldm_x4(ah[mi], sAh32 + off);
                ldm_x4(al[mi], sAl32 + off);
            }
            uint32_t bh[NI][2], bl[NI][2];
#pragma unroll
            for (int ni = 0; ni < NI; ni++) {
                const int row = wc * WN + ni * 8 + (lane & 7);
                const int col = ks + ((lane >> 3) & 1) * 8;
                const uint32_t off = (uint32_t)(row * LDSB + col) * 2;
                ldm_x2(bh[ni], sWh32 + off);
                ldm_x2(bl[ni], sWl32 + off);
            }
#pragma unroll
            for (int mi = 0; mi < MI; mi++)
#pragma unroll
                for (int ni = 0; ni < NI; ni++) {
                    mma16816(acc[mi][ni], ah[mi], bh[ni]);
                    mma16816(acc[mi][ni], ah[mi], bl[ni]);
                    mma16816(acc[mi][ni], al[mi], bh[ni]);
                }
        }
        __syncthreads();
    }

    const int g = lane >> 2, tig = lane & 3;
#pragma unroll
    for (int mi = 0; mi < MI; mi++) {
#pragma unroll
        for (int ni = 0; ni < NI; ni++) {
            const int colg = bn + wc * WN + ni * 8 + tig * 2;
            float v[4] = {acc[mi][ni][0], acc[mi][ni][1],
                          acc[mi][ni][2], acc[mi][ni][3]};
#pragma unroll
            for (int half = 0; half < 2; half++) {
                const int row = bm + wr * WM + mi * 16 + g + half * 8;
                float o0 = v[2 * half], o1 = v[2 * half + 1];
                if (EPI == 0) {
                    *(float2*)&O0[(size_t)row * LDO + colg] = make_float2(o0, o1);
                } else {
                    o0 = o0 / (1.f + __expf(-o0));
                    o1 = o1 / (1.f + __expf(-o1));
                    if (colg < DI_) {
                        *(float2*)&O0[(size_t)row * LDO + colg] = make_float2(o0, o1);
                    } else {
                        *(float2*)&O1[(size_t)row * LDO + colg - DI_] =
                            make_float2(o0, o1);
                    }
                }
            }
        }
    }
}

// ============================================================================
// K2a: dbl = u @ xpw^T  (u fp32 -> bf16 split on the fly during staging).
// ============================================================================
__global__ __launch_bounds__(256) void k2a_gemm(
    const float* __restrict__ U,
    const __nv_bfloat16* __restrict__ Whi, const __nv_bfloat16* __restrict__ Wlo,
    float* __restrict__ DTS, float* __restrict__ BCf)
{
    constexpr int BM = 64, BN = 64;
    constexpr int NI = 4;

    __shared__ __align__(16) __nv_bfloat16 sAh[BM * LDSB];
    __shared__ __align__(16) __nv_bfloat16 sAl[BM * LDSB];
    __shared__ __align__(16) __nv_bfloat16 sWh[BN * LDSB];
    __shared__ __align__(16) __nv_bfloat16 sWl[BN * LDSB];

    const int tid = threadIdx.x;
    const int wid = tid >> 5, lane = tid & 31;
    const int wr = wid >> 1, wc = wid & 1;
    const int bm = blockIdx.x * BM;

    const uint32_t sAh32 = smem_u32(sAh), sAl32 = smem_u32(sAl);
    const uint32_t sWh32 = smem_u32(sWh), sWl32 = smem_u32(sWl);

    float acc[NI][4];
#pragma unroll
    for (int j = 0; j < NI; j++)
#pragma unroll
        for (int e = 0; e < 4; e++) acc[j][e] = 0.f;

    for (int k0 = 0; k0 < DI_; k0 += 32) {
#pragma unroll
        for (int it = 0; it < 2; it++) {
            const int idx = tid + it * 256;
            const int row = idx >> 3, c4 = idx & 7;
            float4 v = *(const float4*)&U[(size_t)(bm + row) * DI_ + k0 + c4 * 4];
            __nv_bfloat162 l0, l1;
            __nv_bfloat162 h0 = split_hi2(v.x, v.y, l0);
            __nv_bfloat162 h1 = split_hi2(v.z, v.w, l1);
            const int so = row * LDSB + c4 * 4;
            *(__nv_bfloat162*)&sAh[so] = h0; *(__nv_bfloat162*)&sAh[so + 2] = h1;
            *(__nv_bfloat162*)&sAl[so] = l0; *(__nv_bfloat162*)&sAl[so + 2] = l1;
        }
#pragma unroll
        for (int idx = tid; idx < BN * 4; idx += 256) {
            const int row = idx >> 2, c = idx & 3;
            const size_t go = (size_t)row * DI_ + k0 + c * 8;
            const int so = row * LDSB + c * 8;
            *(float4*)&sWh[so] = *(const float4*)&Whi[go];
            *(float4*)&sWl[so] = *(const float4*)&Wlo[go];
        }
        __syncthreads();

#pragma unroll
        for (int ks = 0; ks < 32; ks += 16) {
            uint32_t ah[4], al[4];
            {
                const int row = wr * 16 + (lane & 15);
                const int col = ks + ((lane >> 4) << 3);
                const uint32_t off = (uint32_t)(row * LDSB + col) * 2;
                ldm_x4(ah, sAh32 + off);
                ldm_x4(al, sAl32 + off);
            }
            uint32_t bh[NI][2], bl[NI][2];
#pragma unroll
            for (int ni = 0; ni < NI; ni++) {
                const int row = wc * 32 + ni * 8 + (lane & 7);
                const int col = ks + ((lane >> 3) & 1) * 8;
                const uint32_t off = (uint32_t)(row * LDSB + col) * 2;
                ldm_x2(bh[ni], sWh32 + off);
                ldm_x2(bl[ni], sWl32 + off);
            }
#pragma unroll
            for (int ni = 0; ni < NI; ni++) {
                mma16816(acc[ni], ah, bh[ni]);
                mma16816(acc[ni], ah, bl[ni]);
                mma16816(acc[ni], al, bh[ni]);
            }
        }
        __syncthreads();
    }

    const int g = lane >> 2, tig = lane & 3;
#pragma unroll
    for (int ni = 0; ni < NI; ni++) {
        const int colg = wc * 32 + ni * 8 + tig * 2;
#pragma unroll
        for (int half = 0; half < 2; half++) {
            const int row = bm + wr * 16 + g + half * 8;
            const float o0 = acc[ni][2 * half], o1 = acc[ni][2 * half + 1];
            if (colg < R_) {
                *(float2*)&DTS[(size_t)row * R_ + colg] = make_float2(o0, o1);
            } else if (colg < R_ + N_) {
                const int n = colg - R_;
                BCf[(size_t)row * 32 + 2 * n] = o0;
                BCf[(size_t)row * 32 + 2 * n + 2] = o1;
            } else if (colg < NC_) {
                const int n = colg - R_ - N_;
                BCf[(size_t)row * 32 + 2 * n + 1] = o0;
                BCf[(size_t)row * 32 + 2 * n + 3] = o1;
            }
        }
    }
}

// ============================================================================
// K2b: DU = (softplus(dts @ DTW^T + DTB), u)   packed float2
// ============================================================================
__device__ __forceinline__ float softplusf(float x) {
    return (x > 20.f) ? x : log1pf(__expf(x));
}

__global__ __launch_bounds__(256) void k2b_delta(
    const float* __restrict__ DTS, const float* __restrict__ U,
    const float* __restrict__ DTW, const float* __restrict__ DTB,
    float2* __restrict__ DU)
{
    __shared__ float sdtwT[R_][DI_];
    __shared__ float sdts[128 * R_];
    __shared__ float sdtb[DI_];

    const int tid = threadIdx.x;
    const int row0 = blockIdx.x * 128;

    for (int i = tid; i < DI_ * R_; i += 256) {
        int d = i / R_, j = i - d * R_;
        sdtwT[j][d] = DTW[i];
    }
    for (int i = tid; i < 128 * R_; i += 256)
        sdts[i] = DTS[(size_t)row0 * R_ + i];
    for (int i = tid; i < DI_; i += 256) sdtb[i] = DTB[i];
    __syncthreads();

    for (int o = tid; o < 128 * DI_; o += 256) {
        const int r = o / DI_, d = o - r * DI_;
        float acc = sdtb[d];
        const float* ds = &sdts[r * R_];
#pragma unroll
        for (int j = 0; j < R_; j++) acc = fmaf(ds[j], sdtwT[j][d], acc);
        const size_t m = (size_t)(row0 + r) * DI_ + d;
        DU[m] = make_float2(softplusf(acc), U[m]);
    }
}

// ============================================================================
// K3: selective scan — 8 lanes per (b,d) group, 2 states per lane,
//   16-step batches (deep prefetch: next batch's 32 loads in flight during
//   ~400 cyc of compute), butterfly reduction (7 SHFL + 1 STG per 8 steps).
// ============================================================================
#define K3_UNR 16

__device__ __forceinline__ void k3_reduce_store8(
    float* yv, int l, float* yptr, int t0)
{
    // butterfly: 8 values across 8 lanes -> lane l holds sum for t0+l
#pragma unroll
    for (int i = 0; i < 4; i++) {
        float give = (l & 4) ? yv[i] : yv[i + 4];
        float got = __shfl_xor_sync(0xffffffffu, give, 4, 8);
        yv[i] = ((l & 4) ? yv[i + 4] : yv[i]) + got;
    }
#pragma unroll
    for (int i = 0; i < 2; i++) {
        float give = (l & 2) ? yv[i] : yv[i + 2];
        float got = __shfl_xor_sync(0xffffffffu, give, 2, 8);
        yv[i] = ((l & 2) ? yv[i + 2] : yv[i]) + got;
    }
    {
        float give = (l & 1) ? yv[0] : yv[1];
        float got = __shfl_xor_sync(0xffffffffu, give, 1, 8);
        float tot = ((l & 1) ? yv[1] : yv[0]) + got;
        yptr[(size_t)(t0 + l) * DI_] = tot;
    }
}

__global__ __launch_bounds__(32) void k3_scan(
    const float2* __restrict__ DU, const float4* __restrict__ BC4,
    const float* __restrict__ A_logs, const float* __restrict__ Ds,
    float* __restrict__ Y)
{
    const int tid = threadIdx.x;
    const int gid = (blockIdx.x * 32 + tid) >> 3;   // (b,d) group
    const int l = tid & 7;                           // lane-in-group
    const int b = gid / DI_;
    const int d = gid - b * DI_;

    const float A1 = -__expf(A_logs[d * N_ + 2 * l]);
    const float A2 = -__expf(A_logs[d * N_ + 2 * l + 1]);
    const float Dd = Ds[d];

    const float2* duptr = DU + (size_t)b * L_ * DI_ + d;
    const float4* bcptr = BC4 + (size_t)b * L_ * (N_ / 2) + l;
    float* yptr         = Y  + (size_t)b * L_ * DI_ + d;

    float2 duA[K3_UNR], duB[K3_UNR];
    float4 bcA[K3_UNR], bcB[K3_UNR];

#pragma unroll
    for (int j = 0; j < K3_UNR; j++) {
        duA[j] = __ldcs(&duptr[(size_t)j * DI_]);
        bcA[j] = __ldcs(&bcptr[(size_t)j * (N_ / 2)]);
    }

    float h1 = 0.f, h2 = 0.f;
    for (int t0 = 0; t0 < L_; t0 += 2 * K3_UNR) {
        // prefetch next 16 into B
#pragma unroll
        for (int j = 0; j < K3_UNR; j++) {
            duB[j] = __ldcs(&duptr[(size_t)(t0 + K3_UNR + j) * DI_]);
            bcB[j] = __ldcs(&bcptr[(size_t)(t0 + K3_UNR + j) * (N_ / 2)]);
        }
        // compute from A (two 8-step sub-batches)
#pragma unroll
        for (int s = 0; s < K3_UNR; s += 8) {
            float yv[8];
#pragma unroll
            for (int jj = 0; jj < 8; jj++) {
                const int j = s + jj;
                const float e1 = __expf(duA[j].x * A1);
                const float e2 = __expf(duA[j].x * A2);
                const float x = duA[j].x * duA[j].y;
                h1 = fmaf(e1, h1, x * bcA[j].x);
                h2 = fmaf(e2, h2, x * bcA[j].z);
                yv[jj] = fmaf(h1, bcA[j].y, h2 * bcA[j].w);
                yv[jj] += (l == jj) ? Dd * duA[j].y : 0.f;
            }
            k3_reduce_store8(yv, l, yptr, t0 + s);
        }
        // prefetch following 16 into A (guarded, uniform branch)
        if (t0 + 2 * K3_UNR < L_) {
#pragma unroll
            for (int j = 0; j < K3_UNR; j++) {
                duA[j] = __ldcs(&duptr[(size_t)(t0 + 2 * K3_UNR + j) * DI_]);
                bcA[j] = __ldcs(&bcptr[(size_t)(t0 + 2 * K3_UNR + j) * (N_ / 2)]);
            }
        }
        // compute from B
#pragma unroll
        for (int s = 0; s < K3_UNR; s += 8) {
            float yv[8];
#pragma unroll
            for (int jj = 0; jj < 8; jj++) {
                const int j = s + jj;
                const float e1 = __expf(duB[j].x * A1);
                const float e2 = __expf(duB[j].x * A2);
                const float x = duB[j].x * duB[j].y;
                h1 = fmaf(e1, h1, x * bcB[j].x);
                h2 = fmaf(e2, h2, x * bcB[j].z);
                yv[jj] = fmaf(h1, bcB[j].y, h2 * bcB[j].w);
                yv[jj] += (l == jj) ? Dd * duB[j].y : 0.f;
            }
            k3_reduce_store8(yv, l, yptr, t0 + K3_UNR + s);
        }
    }
}

// ============================================================================
// K4a: yln = (LayerNorm(y)*gamma+beta)*z, emitted as bf16 hi/lo split
// ============================================================================
__global__ __launch_bounds__(256) void k4a_ln(
    const float* __restrict__ Y, const float* __restrict__ Zg,
    const float* __restrict__ gamma, const float* __restrict__ beta,
    __nv_bfloat16* __restrict__ Yhi, __nv_bfloat16* __restrict__ Ylo)
{
    const int tid = threadIdx.x;
    const int warp = tid >> 5, lane = tid & 31;
    const int row = blockIdx.x * 8 + warp;

    const float* yr = Y  + (size_t)row * DI_;
    const float* zr = Zg + (size_t)row * DI_;
    __nv_bfloat16* hr = Yhi + (size_t)row * DI_;
    __nv_bfloat16* lr = Ylo + (size_t)row * DI_;

    float v[12];
    float sum = 0.f, sq = 0.f;
#pragma unroll
    for (int i = 0; i < 12; i++) {
        float t = yr[lane + i * 32];
        v[i] = t; sum += t; sq = fmaf(t, t, sq);
    }
#pragma unroll
    for (int o = 16; o; o >>= 1) {
        sum += __shfl_xor_sync(0xffffffffu, sum, o);
        sq  += __shfl_xor_sync(0xffffffffu, sq, o);
    }
    const float mu = sum * (1.f / DI_);
    const float var = sq * (1.f / DI_) - mu * mu;
    const float rs = rsqrtf(var + 1e-5f);
#pragma unroll
    for (int i = 0; i < 12; i++) {
        int k = lane + i * 32;
        float r = fmaf((v[i] - mu) * rs, gamma[k], beta[k]) * zr[k];
        __nv_bfloat16 h = __float2bfloat16_rn(r);
        hr[k] = h;
        lr[k] = __float2bfloat16_rn(r - __bfloat162float(h));
    }
}

// ============================================================================
extern "C" void kernel_launch(void* const* d_in, const int* in_sizes, int n_in,
                              void* d_out, int out_size)
{
    const float* x         = (const float*)d_in[0];
    const float* W_in      = (const float*)d_in[1];
    const float* x_proj_w  = (const float*)d_in[2];
    const float* dt_proj_w = (const float*)d_in[3];
    const float* dt_proj_b = (const float*)d_in[4];
    const float* A_logs    = (const float*)d_in[5];
    const float* Ds        = (const float*)d_in[6];
    const float* ln_gamma  = (const float*)d_in[7];
    const float* ln_beta   = (const float*)d_in[8];
    const float* W_out     = (const float*)d_in[9];
    float* out = (float*)d_out;

    float *u, *z, *dts, *y;
    float2 *du, *bc;
    __nv_bfloat16 *xhi, *xlo, *whi, *wlo, *xpwhi, *xpwlo;
    __nv_bfloat16 *yhi, *ylo, *wohi, *wolo;
    cudaGetSymbolAddress((void**)&u, g_u);
    cudaGetSymbolAddress((void**)&z, g_z);
    cudaGetSymbolAddress((void**)&dts, g_dts);
    cudaGetSymbolAddress((void**)&du, g_DU);
    cudaGetSymbolAddress((void**)&bc, g_BC);
    cudaGetSymbolAddress((void**)&y, g_y);
    cudaGetSymbolAddress((void**)&xhi, g_xhi);
    cudaGetSymbolAddress((void**)&xlo, g_xlo);
    cudaGetSymbolAddress((void**)&whi, g_whi);
    cudaGetSymbolAddress((void**)&wlo, g_wlo);
    cudaGetSymbolAddress((void**)&xpwhi, g_xpwhi);
    cudaGetSymbolAddress((void**)&xpwlo, g_xpwlo);
    cudaGetSymbolAddress((void**)&yhi, g_yhi);
    cudaGetSymbolAddress((void**)&ylo, g_ylo);
    cudaGetSymbolAddress((void**)&wohi, g_wohi);
    cudaGetSymbolAddress((void**)&wolo, g_wolo);

    // input conversions
    conv_split<<<(M_ * DM_ / 4 + 255) / 256, 256>>>(x, xhi, xlo, M_ * DM_ / 4);
    conv_split<<<(NXZ_ * DM_ / 4 + 255) / 256, 256>>>(W_in, whi, wlo, NXZ_ * DM_ / 4);
    conv_split_pad44<<<(NCPAD_ * DI_ / 4 + 255) / 256, 256>>>(x_proj_w, xpwhi, xpwlo);

    // K1: u|z = silu(x @ W_in^T)
    dim3 g1(M_ / 128, NXZ_ / 128);
    gemm_mma<128, 128, DM_, 1, DI_><<<g1, 256>>>(xhi, xlo, whi, wlo, u, z);

    // K2a: dbl = u @ xpw^T -> dts | BC packed
    k2a_gemm<<<M_ / 64, 256>>>(u, xpwhi, xpwlo, dts, (float*)bc);

    // K2b: DU = (softplus(dts @ dtw^T + b), u)
    k2b_delta<<<M_ / 128, 256>>>(dts, u, dt_proj_w, dt_proj_b, du);

    // K3: scan — deep-prefetch (16-step batches), butterfly-reduced
    k3_scan<<<(NGRP * 8) / 32, 32>>>(du, (const float4*)bc, A_logs, Ds, y);

    conv_split<<<(DM_ * DI_ / 4 + 255) / 256, 256>>>(W_out, wohi, wolo, DM_ * DI_ / 4);

    k4a_ln<<<M_ / 8, 256>>>(y, z, ln_gamma, ln_beta, yhi, ylo);

    // K4b: out = yln @ W_out^T
    dim3 g4(M_ / 128, DM_ / 64);
    gemm_mma<128, 64, DI_, 0, DM_><<<g4, 256>>>(yhi, ylo, wohi, wolo, out, nullptr);
}